// round 5
// baseline (speedup 1.0000x reference)
#include <cuda_runtime.h>
#include <cstdint>
#include <cstdio>

#define VOCAB 50257
#define EMB   64
#define HID   32
#define SEQL  256
#define BATCH 16
#define MROWS 4096          // SEQL*BATCH
#define GDIM  96            // 3*HID
#define KDIM  64            // 2*HID
#define NB_PAD 6288         // padded number of 8-col blocks (393*16)
#define NCHUNK 393          // 128-col chunks covering vocab

// ---------------- device scratch (static globals; no allocation) ----------------
__device__ float g_gx[2 * MROWS * GDIM];        // 3.1 MB  precomputed input gates
__device__ float g_h[MROWS * KDIM];             // 1 MB    concat hidden (tf32-rounded)
__device__ float g_Ap[256 * 8 * 32 * 4];        // 1 MB    A in mma-fragment layout
__device__ float g_Wp[NB_PAD * 512];            // 12.9 MB W in mma-fragment layout (tf32)
__device__ float g_partial[MROWS * NCHUNK];     // 6.4 MB  per-chunk exp-sums
__device__ float g_lse[MROWS];

// ---------------- helpers ----------------
__device__ __forceinline__ float tf32r(float x) {
    float r;
    asm("cvt.rna.tf32.f32 %0, %1;" : "=f"(r) : "f"(x));
    return r;
}
__device__ __forceinline__ uint32_t fasu(float x) { return __float_as_uint(x); }

__device__ __forceinline__ void mma_tf32(float c[4], const uint32_t a[4], const uint32_t b[2]) {
    asm volatile(
        "mma.sync.aligned.m16n8k8.row.col.f32.tf32.tf32.f32 "
        "{%0,%1,%2,%3},{%4,%5,%6,%7},{%8,%9},{%0,%1,%2,%3};"
        : "+f"(c[0]), "+f"(c[1]), "+f"(c[2]), "+f"(c[3])
        : "r"(a[0]), "r"(a[1]), "r"(a[2]), "r"(a[3]), "r"(b[0]), "r"(b[1]));
}

// ---------------- kernel: repack W (64 x VOCAB) into tf32 fragment layout ----------------
// Wp[((nb*8+kb)*32+lane)*2 + {0,1}] : b0 = W[kb*8+t][nb*8+g], b1 = W[kb*8+t+4][nb*8+g]
__global__ void k_prep_w(const float* __restrict__ W) {
    int idx = blockIdx.x * 256 + threadIdx.x;   // < NB_PAD*8*32 = 1,609,728
    int l  = idx & 31;
    int kb = (idx >> 5) & 7;
    int nb = idx >> 8;
    int col = nb * 8 + (l >> 2);
    int r   = kb * 8 + (l & 3);
    float v0 = 0.f, v1 = 0.f;
    if (col < VOCAB) {
        v0 = W[r * VOCAB + col];
        v1 = W[(r + 4) * VOCAB + col];
    }
    g_Wp[idx * 2]     = tf32r(v0);
    g_Wp[idx * 2 + 1] = tf32r(v1);
}

// ---------------- kernel: embedding + gx = x@W_ih + b_ih for both directions ----------------
// block = 96 threads (thread j = gate column), 16 (s,b) pairs per block
__global__ void k_gx(const int* __restrict__ tok, const float* __restrict__ emb,
                     const float* __restrict__ Wl, const float* __restrict__ bl,
                     const float* __restrict__ Wr, const float* __restrict__ br) {
    int j = threadIdx.x;   // 0..95
    float wl[64], wr[64];
#pragma unroll
    for (int k = 0; k < 64; k++) {
        wl[k] = Wl[k * GDIM + j];
        wr[k] = Wr[k * GDIM + j];
    }
    float blv = bl[j], brv = br[j];
    __shared__ float xs[64];
    int p0 = blockIdx.x * 16;
    for (int i = 0; i < 16; i++) {
        int p = p0 + i;
        int t = __ldg(&tok[p]);
        __syncthreads();
        if (j < 64) xs[j] = emb[t * EMB + j];
        __syncthreads();
        float al = blv, ar = brv;
#pragma unroll
        for (int k = 0; k < 64; k++) {
            al = fmaf(xs[k], wl[k], al);
            ar = fmaf(xs[k], wr[k], ar);
        }
        g_gx[(size_t)p * GDIM + j]                        = al;
        g_gx[(size_t)(MROWS + p) * GDIM + j]              = ar;
    }
}

// ---------------- kernel: GRU recurrence, one block per (dir, batch) ----------------
__global__ void k_scan(const float* __restrict__ Wlhh, const float* __restrict__ blhh,
                       const float* __restrict__ Wrhh, const float* __restrict__ brhh) {
    int bx = blockIdx.x;
    int d = bx >> 4, b = bx & 15;
    int j = threadIdx.x;   // 0..95
    const float* Whh = d ? Wrhh : Wlhh;
    const float* bhh = d ? brhh : blhh;
    float wh[32];
#pragma unroll
    for (int k = 0; k < 32; k++) wh[k] = Whh[k * GDIM + j];
    float bh = bhh[j];

    __shared__ float hs[32];
    __shared__ float ghs[96];
    __shared__ float gxs[96];
    if (j < 32) hs[j] = 0.f;
    __syncthreads();

    const float* gx = g_gx + (size_t)d * MROWS * GDIM;
    int s = d ? (SEQL - 1) : 0;
    int step = d ? -1 : 1;
    float gxv = __ldg(&gx[(size_t)(s * BATCH + b) * GDIM + j]);

    for (int i = 0; i < SEQL; i++) {
        float gxn = 0.f;
        if (i < SEQL - 1) gxn = __ldg(&gx[(size_t)((s + step) * BATCH + b) * GDIM + j]);
        float acc = bh;
#pragma unroll
        for (int k = 0; k < 32; k++) acc = fmaf(hs[k], wh[k], acc);
        ghs[j] = acc;
        gxs[j] = gxv;
        __syncthreads();
        if (j < 32) {
            float r = 1.f / (1.f + __expf(-(gxs[j] + ghs[j])));
            float z = 1.f / (1.f + __expf(-(gxs[32 + j] + ghs[32 + j])));
            float n = tanhf(gxs[64 + j] + r * ghs[64 + j]);
            float hn = (1.f - z) * n + z * hs[j];
            hs[j] = hn;
            g_h[(size_t)(s * BATCH + b) * KDIM + d * HID + j] = tf32r(hn);
        }
        __syncthreads();
        gxv = gxn;
        s += step;
    }
}

// ---------------- kernel: repack A (h) into mma-fragment layout ----------------
__global__ void k_repack() {
    int idx = blockIdx.x * 256 + threadIdx.x;  // < 65536
    int l  = idx & 31;
    int kb = (idx >> 5) & 7;
    int mi = idx >> 8;
    int g = l >> 2, t = l & 3;
    int r0 = mi * 16 + g;
    int c0 = kb * 8 + t;
    float4 v;
    v.x = g_h[r0 * KDIM + c0];
    v.y = g_h[(r0 + 8) * KDIM + c0];
    v.z = g_h[r0 * KDIM + c0 + 4];
    v.w = g_h[(r0 + 8) * KDIM + c0 + 4];
    ((float4*)g_Ap)[idx] = v;
}

// ---------------- GEMM: C = A(4096x64) * W(64xVOCAB), tiled 128x128 per CTA ----------------
// PASSB==0: accumulate per-row sum(exp(logit+bias)) into g_partial
// PASSB==1: write out = logit + bias - lse
template <int PASSB>
__global__ void __launch_bounds__(256, 2) k_gemm(const float* __restrict__ bias,
                                                 float* __restrict__ out) {
    extern __shared__ float sm[];
    float* Bs     = sm;            // 8192 floats
    float* As     = sm + 8192;     // 8192 floats
    float* bias_s = sm + 16384;    // 128
    float* lse_s  = sm + 16512;    // 128

    int tid = threadIdx.x;
    int warp = tid >> 5, lane = tid & 31;
    int wm = warp & 3, wn = warp >> 2;
    int mb = blockIdx.y, ch = blockIdx.x;

    const float4* Bsrc = ((const float4*)g_Wp) + (size_t)ch * 2048;
    float4* Bs4 = (float4*)Bs;
    const float4* Asrc = ((const float4*)g_Ap) + (size_t)mb * 2048;
    float4* As4 = (float4*)As;
#pragma unroll
    for (int i = 0; i < 8; i++) {
        Bs4[tid + i * 256] = Bsrc[tid + i * 256];
        As4[tid + i * 256] = Asrc[tid + i * 256];
    }
    if (tid < 128) {
        int col = ch * 128 + tid;
        bias_s[tid] = (col < VOCAB) ? bias[col] : -1e30f;
        if (PASSB) lse_s[tid] = g_lse[mb * 128 + tid];
    }
    __syncthreads();

    float c[2][8][4];
#pragma unroll
    for (int mf = 0; mf < 2; mf++)
#pragma unroll
        for (int nf = 0; nf < 8; nf++)
#pragma unroll
            for (int q = 0; q < 4; q++) c[mf][nf][q] = 0.f;

    const float2* Bs2 = (const float2*)Bs;
#pragma unroll
    for (int kb = 0; kb < 8; kb++) {
        uint32_t a[2][4];
#pragma unroll
        for (int mf = 0; mf < 2; mf++) {
            float4 av = As4[((wm * 2 + mf) * 8 + kb) * 32 + lane];
            a[mf][0] = fasu(av.x); a[mf][1] = fasu(av.y);
            a[mf][2] = fasu(av.z); a[mf][3] = fasu(av.w);
        }
#pragma unroll
        for (int nf = 0; nf < 8; nf++) {
            float2 bv = Bs2[((wn * 8 + nf) * 8 + kb) * 32 + lane];
            uint32_t bu[2] = {fasu(bv.x), fasu(bv.y)};
            mma_tf32(c[0][nf], a[0], bu);
            mma_tf32(c[1][nf], a[1], bu);
        }
    }

    int g = lane >> 2, t = lane & 3;
    if (!PASSB) {
        float rs[2][2] = {{0.f, 0.f}, {0.f, 0.f}};
#pragma unroll
        for (int mf = 0; mf < 2; mf++)
#pragma unroll
            for (int nf = 0; nf < 8; nf++) {
                int cl = (wn * 8 + nf) * 8 + 2 * t;
                rs[mf][0] += __expf(c[mf][nf][0] + bias_s[cl]) + __expf(c[mf][nf][1] + bias_s[cl + 1]);
                rs[mf][1] += __expf(c[mf][nf][2] + bias_s[cl]) + __expf(c[mf][nf][3] + bias_s[cl + 1]);
            }
#pragma unroll
        for (int o = 1; o <= 2; o <<= 1) {
            rs[0][0] += __shfl_xor_sync(0xffffffffu, rs[0][0], o);
            rs[0][1] += __shfl_xor_sync(0xffffffffu, rs[0][1], o);
            rs[1][0] += __shfl_xor_sync(0xffffffffu, rs[1][0], o);
            rs[1][1] += __shfl_xor_sync(0xffffffffu, rs[1][1], o);
        }
        __syncthreads();               // all warps done reading As/Bs
        float* rsum = As;              // reuse
        if (t == 0) {
#pragma unroll
            for (int mf = 0; mf < 2; mf++) {
                int rl = wm * 32 + mf * 16 + g;
                rsum[wn * 128 + rl]     = rs[mf][0];
                rsum[wn * 128 + rl + 8] = rs[mf][1];
            }
        }
        __syncthreads();
        if (tid < 128)
            g_partial[(size_t)(mb * 128 + tid) * NCHUNK + ch] = rsum[tid] + rsum[128 + tid];
    } else {
#pragma unroll
        for (int mf = 0; mf < 2; mf++) {
            int rl = wm * 32 + mf * 16 + g;
            float l0 = lse_s[rl], l1 = lse_s[rl + 8];
            size_t r0 = (size_t)(mb * 128 + rl) * VOCAB;
            size_t r1 = r0 + (size_t)8 * VOCAB;
#pragma unroll
            for (int nf = 0; nf < 8; nf++) {
                int cl = (wn * 8 + nf) * 8 + 2 * t;
                int col = ch * 128 + cl;
                if (col < VOCAB) {
                    out[r0 + col] = c[mf][nf][0] + bias_s[cl] - l0;
                    out[r1 + col] = c[mf][nf][2] + bias_s[cl] - l1;
                }
                if (col + 1 < VOCAB) {
                    out[r0 + col + 1] = c[mf][nf][1] + bias_s[cl + 1] - l0;
                    out[r1 + col + 1] = c[mf][nf][3] + bias_s[cl + 1] - l1;
                }
            }
        }
    }
}

// ---------------- kernel: lse[row] = log(sum of chunk partials) ----------------
__global__ void k_lse() {
    int w = (blockIdx.x * blockDim.x + threadIdx.x) >> 5;   // row, 0..4095
    int lane = threadIdx.x & 31;
    float s = 0.f;
    for (int c = lane; c < NCHUNK; c += 32) s += g_partial[(size_t)w * NCHUNK + c];
#pragma unroll
    for (int o = 16; o; o >>= 1) s += __shfl_xor_sync(0xffffffffu, s, o);
    if (lane == 0) g_lse[w] = logf(s);
}

// ---------------- launch ----------------
extern "C" void kernel_launch(void* const* d_in, const int* in_sizes, int n_in,
                              void* d_out, int out_size) {
    const int*   tok    = (const int*)d_in[0];
    const float* emb    = (const float*)d_in[1];
    const float* W_out  = (const float*)d_in[2];
    const float* bias   = (const float*)d_in[3];
    const float* Wl_ih  = (const float*)d_in[4];
    const float* Wl_hh  = (const float*)d_in[5];
    const float* bl_ih  = (const float*)d_in[6];
    const float* bl_hh  = (const float*)d_in[7];
    const float* Wr_ih  = (const float*)d_in[8];
    const float* Wr_hh  = (const float*)d_in[9];
    const float* br_ih  = (const float*)d_in[10];
    const float* br_hh  = (const float*)d_in[11];
    float* out = (float*)d_out;

    const int smem = (8192 + 8192 + 128 + 128) * 4;  // 66560 B
    cudaFuncSetAttribute(k_gemm<0>, cudaFuncAttributeMaxDynamicSharedMemorySize, smem);
    cudaFuncSetAttribute(k_gemm<1>, cudaFuncAttributeMaxDynamicSharedMemorySize, smem);

    k_prep_w<<<NB_PAD, 256>>>(W_out);
    k_gx<<<MROWS / 16, 96>>>(tok, emb, Wl_ih, bl_ih, Wr_ih, br_ih);
    k_scan<<<32, 96>>>(Wl_hh, bl_hh, Wr_hh, br_hh);
    k_repack<<<256, 256>>>();

    dim3 gridG(NCHUNK, MROWS / 128);
    k_gemm<0><<<gridG, 256, smem>>>(bias, nullptr);
    k_lse<<<512, 256>>>();
    k_gemm<1><<<gridG, 256, smem>>>(bias, out);
}

// round 7
// speedup vs baseline: 1.2252x; 1.2252x over previous
#include <cuda_runtime.h>
#include <cuda_bf16.h>
#include <cstdint>
#include <cstdio>

#define VOCAB 50257
#define EMB   64
#define HID   32
#define SEQL  256
#define BATCH 16
#define MROWS 4096          // SEQL*BATCH
#define GDIM  96            // 3*HID
#define KDIM  64            // 2*HID
#define NCHUNK 393          // 128-col chunks covering vocab (393*128 = 50304)
#define MBLK   32           // 4096/128
#define NB_PAD (NCHUNK * 16) // 6288 8-col blocks (padded)

// ---------------- device scratch (static; no allocation) ----------------
__device__ float g_gx[2 * MROWS * GDIM];        // 3.1 MB  precomputed input gates
__device__ float g_h[MROWS * KDIM];             // 1 MB    concat hidden (fp32)
__device__ uint4 g_Ap[MBLK * 1024];             // 512 KB  A bf16 fragments (m16n8k16)
__device__ uint2 g_Bp[NB_PAD * 4 * 32];         // 6.4 MB  W bf16 fragments (m16n8k16)
__device__ float g_partial[MROWS * NCHUNK];     // 6.4 MB  per-chunk exp-sums
__device__ float g_lse[MROWS];

// ---------------- helpers ----------------
__device__ __forceinline__ uint32_t pack_bf16x2(float lo, float hi) {
    __nv_bfloat16 a = __float2bfloat16(lo), b = __float2bfloat16(hi);
    return (uint32_t)__bfloat16_as_ushort(a) | ((uint32_t)__bfloat16_as_ushort(b) << 16);
}

__device__ __forceinline__ void mma_bf16(float c[4], const uint4 a, const uint2 b) {
    asm volatile(
        "mma.sync.aligned.m16n8k16.row.col.f32.bf16.bf16.f32 "
        "{%0,%1,%2,%3},{%4,%5,%6,%7},{%8,%9},{%0,%1,%2,%3};"
        : "+f"(c[0]), "+f"(c[1]), "+f"(c[2]), "+f"(c[3])
        : "r"(a.x), "r"(a.y), "r"(a.z), "r"(a.w), "r"(b.x), "r"(b.y));
}

// ---------------- prep: W (64 x VOCAB) -> bf16 B fragments ----------------
// For nb (8 cols), kb (16 rows), lane: g=lane>>2 (n), t=lane&3 (k pair)
// b0 = {W[kb*16+2t][n], W[kb*16+2t+1][n]}, b1 = {W[kb*16+2t+8][n], W[kb*16+2t+9][n]}
__global__ void k_prep_w(const float* __restrict__ W) {
    int idx = blockIdx.x * 256 + threadIdx.x;   // NB_PAD*4*32 = 804864
    int lane = idx & 31;
    int kb   = (idx >> 5) & 3;
    int nb   = idx >> 7;
    int g = lane >> 2, t = lane & 3;
    int col = nb * 8 + g;
    int k0 = kb * 16 + 2 * t;
    float w0 = 0.f, w1 = 0.f, w2 = 0.f, w3 = 0.f;
    if (col < VOCAB) {
        w0 = W[(size_t)k0 * VOCAB + col];
        w1 = W[(size_t)(k0 + 1) * VOCAB + col];
        w2 = W[(size_t)(k0 + 8) * VOCAB + col];
        w3 = W[(size_t)(k0 + 9) * VOCAB + col];
    }
    uint2 v;
    v.x = pack_bf16x2(w0, w1);
    v.y = pack_bf16x2(w2, w3);
    g_Bp[idx] = v;
}

// ---------------- embedding + gx = x@W_ih + b_ih, both directions ----------------
__global__ void k_gx(const int* __restrict__ tok, const float* __restrict__ emb,
                     const float* __restrict__ Wl, const float* __restrict__ bl,
                     const float* __restrict__ Wr, const float* __restrict__ br) {
    int j = threadIdx.x;   // 0..95
    float wl[64], wr[64];
#pragma unroll
    for (int k = 0; k < 64; k++) {
        wl[k] = Wl[k * GDIM + j];
        wr[k] = Wr[k * GDIM + j];
    }
    float blv = bl[j], brv = br[j];
    __shared__ float xs[64];
    int p0 = blockIdx.x * 16;
    for (int i = 0; i < 16; i++) {
        int p = p0 + i;
        int t = __ldg(&tok[p]);
        __syncthreads();
        if (j < 64) xs[j] = emb[t * EMB + j];
        __syncthreads();
        float al = blv, ar = brv;
#pragma unroll
        for (int k = 0; k < 64; k++) {
            al = fmaf(xs[k], wl[k], al);
            ar = fmaf(xs[k], wr[k], ar);
        }
        g_gx[(size_t)p * GDIM + j]           = al;
        g_gx[(size_t)(MROWS + p) * GDIM + j] = ar;
    }
}

// ---------------- GRU recurrence, one block per (dir, batch) ----------------
__global__ void k_scan(const float* __restrict__ Wlhh, const float* __restrict__ blhh,
                       const float* __restrict__ Wrhh, const float* __restrict__ brhh) {
    int bx = blockIdx.x;
    int d = bx >> 4, b = bx & 15;
    int j = threadIdx.x;   // 0..95
    const float* Whh = d ? Wrhh : Wlhh;
    const float* bhh = d ? brhh : blhh;
    float wh[32];
#pragma unroll
    for (int k = 0; k < 32; k++) wh[k] = Whh[k * GDIM + j];
    float bh = bhh[j];

    __shared__ float hs[32];
    __shared__ float ghs[96];
    __shared__ float gxs[96];
    if (j < 32) hs[j] = 0.f;
    __syncthreads();

    const float* gx = g_gx + (size_t)d * MROWS * GDIM;
    int s = d ? (SEQL - 1) : 0;
    int step = d ? -1 : 1;
    float gxv = __ldg(&gx[(size_t)(s * BATCH + b) * GDIM + j]);

    for (int i = 0; i < SEQL; i++) {
        float gxn = 0.f;
        if (i < SEQL - 1) gxn = __ldg(&gx[(size_t)((s + step) * BATCH + b) * GDIM + j]);
        float acc = bh;
#pragma unroll
        for (int k = 0; k < 32; k++) acc = fmaf(hs[k], wh[k], acc);
        ghs[j] = acc;
        gxs[j] = gxv;
        __syncthreads();
        if (j < 32) {
            float r = 1.f / (1.f + __expf(-(gxs[j] + ghs[j])));
            float z = 1.f / (1.f + __expf(-(gxs[32 + j] + ghs[32 + j])));
            float n = tanhf(gxs[64 + j] + r * ghs[64 + j]);
            float hn = (1.f - z) * n + z * hs[j];
            hs[j] = hn;
            g_h[(size_t)(s * BATCH + b) * KDIM + d * HID + j] = hn;
        }
        __syncthreads();
        gxv = gxn;
        s += step;
    }
}

// ---------------- prep: A (h, 4096x64) -> bf16 A fragments (m16n8k16) ----------------
// a0={A[g][2t],A[g][2t+1]}, a1={A[g+8][..]}, a2={A[g][2t+8..]}, a3={A[g+8][2t+8..]}
__global__ void k_repack() {
    int idx = blockIdx.x * 256 + threadIdx.x;  // 256 mi * 4 kb * 32 = 32768
    int lane = idx & 31;
    int kb   = (idx >> 5) & 3;
    int mi   = idx >> 7;
    int g = lane >> 2, t = lane & 3;
    int row0 = mi * 16 + g;
    int k0 = kb * 16 + 2 * t;
    const float* h0 = g_h + (size_t)row0 * KDIM;
    const float* h8 = h0 + (size_t)8 * KDIM;
    uint4 v;
    v.x = pack_bf16x2(h0[k0], h0[k0 + 1]);
    v.y = pack_bf16x2(h8[k0], h8[k0 + 1]);
    v.z = pack_bf16x2(h0[k0 + 8], h0[k0 + 9]);
    v.w = pack_bf16x2(h8[k0 + 8], h8[k0 + 9]);
    g_Ap[idx] = v;
}

// ---------------- GEMM: C = A(4096x64) * W(64xVOCAB), CTA tile 128x128 ----------------
// bf16 m16n8k16, K=64 -> 4 kb steps; warp tile 32x64 (mf 0-1, nf 0-7)
// PASSB==0: accumulate per-row sum(exp(logit+bias)) into g_partial
// PASSB==1: write out = logit + bias - lse
template <int PASSB>
__global__ void __launch_bounds__(256, 2) k_gemm(const float* __restrict__ bias,
                                                 float* __restrict__ out) {
    __shared__ uint4 As[1024];      // 16 KB: 8 mi x 4 kb x 32 lanes
    __shared__ uint2 Bs[2048];      // 16 KB: 16 nb x 4 kb x 32 lanes
    __shared__ float bias_s[128];
    __shared__ float lse_s[128];
    __shared__ float rsum[256];

    int tid = threadIdx.x;
    int warp = tid >> 5, lane = tid & 31;
    int wm = warp & 3, wn = warp >> 2;
    int mb = blockIdx.y, ch = blockIdx.x;

    const uint4* Asrc = g_Ap + (size_t)mb * 1024;
    const uint4* Bsrc = (const uint4*)(g_Bp + (size_t)ch * 2048);
    uint4* Bs4 = (uint4*)Bs;
#pragma unroll
    for (int i = 0; i < 4; i++) {
        As[tid + i * 256]  = Asrc[tid + i * 256];
        Bs4[tid + i * 256] = Bsrc[tid + i * 256];
    }
    if (tid < 128) {
        int col = ch * 128 + tid;
        bias_s[tid] = (col < VOCAB) ? bias[col] : -1e30f;
        if (PASSB) lse_s[tid] = g_lse[mb * 128 + tid];
    }
    __syncthreads();

    float c[2][8][4];
#pragma unroll
    for (int mf = 0; mf < 2; mf++)
#pragma unroll
        for (int nf = 0; nf < 8; nf++)
#pragma unroll
            for (int q = 0; q < 4; q++) c[mf][nf][q] = 0.f;

#pragma unroll
    for (int kb = 0; kb < 4; kb++) {
        uint4 a[2];
#pragma unroll
        for (int mf = 0; mf < 2; mf++)
            a[mf] = As[((wm * 2 + mf) * 4 + kb) * 32 + lane];
#pragma unroll
        for (int nf = 0; nf < 8; nf++) {
            uint2 b = Bs[((wn * 8 + nf) * 4 + kb) * 32 + lane];
            mma_bf16(c[0][nf], a[0], b);
            mma_bf16(c[1][nf], a[1], b);
        }
    }

    int g = lane >> 2, t = lane & 3;
    if (!PASSB) {
        float rs[2][2] = {{0.f, 0.f}, {0.f, 0.f}};
#pragma unroll
        for (int mf = 0; mf < 2; mf++)
#pragma unroll
            for (int nf = 0; nf < 8; nf++) {
                int cl = (wn * 8 + nf) * 8 + 2 * t;
                rs[mf][0] += __expf(c[mf][nf][0] + bias_s[cl]) + __expf(c[mf][nf][1] + bias_s[cl + 1]);
                rs[mf][1] += __expf(c[mf][nf][2] + bias_s[cl]) + __expf(c[mf][nf][3] + bias_s[cl + 1]);
            }
#pragma unroll
        for (int o = 1; o <= 2; o <<= 1) {
            rs[0][0] += __shfl_xor_sync(0xffffffffu, rs[0][0], o);
            rs[0][1] += __shfl_xor_sync(0xffffffffu, rs[0][1], o);
            rs[1][0] += __shfl_xor_sync(0xffffffffu, rs[1][0], o);
            rs[1][1] += __shfl_xor_sync(0xffffffffu, rs[1][1], o);
        }
        if (t == 0) {
#pragma unroll
            for (int mf = 0; mf < 2; mf++) {
                int rl = wm * 32 + mf * 16 + g;
                rsum[wn * 128 + rl]     = rs[mf][0];
                rsum[wn * 128 + rl + 8] = rs[mf][1];
            }
        }
        __syncthreads();
        if (tid < 128)
            g_partial[(size_t)(mb * 128 + tid) * NCHUNK + ch] = rsum[tid] + rsum[128 + tid];
    } else {
#pragma unroll
        for (int mf = 0; mf < 2; mf++) {
            int rl = wm * 32 + mf * 16 + g;
            float l0 = lse_s[rl], l1 = lse_s[rl + 8];
            size_t r0 = (size_t)(mb * 128 + rl) * VOCAB;
            size_t r1 = r0 + (size_t)8 * VOCAB;
#pragma unroll
            for (int nf = 0; nf < 8; nf++) {
                int cl = (wn * 8 + nf) * 8 + 2 * t;
                int col = ch * 128 + cl;
                if (col < VOCAB) {
                    out[r0 + col] = c[mf][nf][0] + bias_s[cl] - l0;
                    out[r1 + col] = c[mf][nf][2] + bias_s[cl] - l1;
                }
                if (col + 1 < VOCAB) {
                    out[r0 + col + 1] = c[mf][nf][1] + bias_s[cl + 1] - l0;
                    out[r1 + col + 1] = c[mf][nf][3] + bias_s[cl + 1] - l1;
                }
            }
        }
    }
}

// ---------------- lse[row] = log(sum of chunk partials) ----------------
__global__ void k_lse() {
    int w = (blockIdx.x * blockDim.x + threadIdx.x) >> 5;   // row, 0..4095
    int lane = threadIdx.x & 31;
    float s = 0.f;
    for (int c = lane; c < NCHUNK; c += 32) s += g_partial[(size_t)w * NCHUNK + c];
#pragma unroll
    for (int o = 16; o; o >>= 1) s += __shfl_xor_sync(0xffffffffu, s, o);
    if (lane == 0) g_lse[w] = logf(s);
}

// ---------------- launch ----------------
extern "C" void kernel_launch(void* const* d_in, const int* in_sizes, int n_in,
                              void* d_out, int out_size) {
    const int*   tok    = (const int*)d_in[0];
    const float* emb    = (const float*)d_in[1];
    const float* W_out  = (const float*)d_in[2];
    const float* bias   = (const float*)d_in[3];
    const float* Wl_ih  = (const float*)d_in[4];
    const float* Wl_hh  = (const float*)d_in[5];
    const float* bl_ih  = (const float*)d_in[6];
    const float* bl_hh  = (const float*)d_in[7];
    const float* Wr_ih  = (const float*)d_in[8];
    const float* Wr_hh  = (const float*)d_in[9];
    const float* br_ih  = (const float*)d_in[10];
    const float* br_hh  = (const float*)d_in[11];
    float* out = (float*)d_out;

    k_prep_w<<<NB_PAD * 4 * 32 / 256, 256>>>(W_out);
    k_gx<<<MROWS / 16, 96>>>(tok, emb, Wl_ih, bl_ih, Wr_ih, br_ih);
    k_scan<<<32, 96>>>(Wl_hh, bl_hh, Wr_hh, br_hh);
    k_repack<<<128, 256>>>();

    dim3 gridG(NCHUNK, MBLK);
    k_gemm<0><<<gridG, 256>>>(bias, nullptr);
    k_lse<<<512, 256>>>();
    k_gemm<1><<<gridG, 256>>>(bias, out);
}